// round 10
// baseline (speedup 1.0000x reference)
#include <cuda_runtime.h>
#include <cstdint>

// Problem constants (SLEN=208, PTILE=8, STEP=2, EDGE=3, MAXDET=2)
#define BATCH 16
#define NSRC  100
#define NFLUX 5
#define NT    101                 // tiles per dim
#define PT    (NT * NT)           // 10201
#define BP    (BATCH * PT)        // 163216
// Output sections (float32, concatenated):
//   n [BP] | locs [BP*4] | fluxes [BP*10] | is_on [BP*2]
#define OFF_L (BP)                 // 163216  (mult of 4)
#define OFF_F (OFF_L + BP * 4)     // 816080  (mult of 4)
#define OFF_I (OFF_F + BP * 10)    // 2448240 (mult of 4)

#define TPB    256
#define NWARP  (TPB / 32)
#define CHUNK  276                         // mult of 4, < PT (spans <= 2 batches)
#define GRID   ((BP + CHUNK - 1) / CHUNK)  // 592: 4 blocks/SM, single wave

// SMEM staging layout (floats): N | L | F | I, all 16B-aligned
#define SM_N   0
#define SM_L   (CHUNK)                     // 276
#define SM_F   (SM_L + 4 * CHUNK)          // 1380
#define SM_I   (SM_F + 10 * CHUNK)         // 4140
#define SM_TOT (SM_I + 2 * CHUNK)          // 4692 floats = 18768 B

__device__ __forceinline__ uint32_t smem_u32(const void* p) {
    return (uint32_t)__cvta_generic_to_shared(p);
}
__device__ __forceinline__ void bulk_store_s2g(void* gdst, uint32_t ssrc, uint32_t bytes) {
    asm volatile("cp.async.bulk.global.shared::cta.bulk_group [%0], [%1], %2;"
                 :: "l"(gdst), "r"(ssrc), "r"(bytes) : "memory");
}

// Map pixel coords -> (tile, fx, fy); returns tile or -1. Bit-identical to R1.
__device__ __forceinline__ int map_source(float l0, float l1, float& fx, float& fy) {
    float p0 = l0 * 207.0f;                                  // SLEN-1
    float p1 = l1 * 207.0f;
    int kx = (int)floorf((p0 - 2.5f) * 0.5f);
    int ky = (int)floorf((p1 - 2.5f) * 0.5f);
    float lx = 2.0f * (float)kx + 2.5f;                      // exact fp32
    float ly = 2.0f * (float)ky + 2.5f;
    bool v0 = (kx >= 0) && (kx < NT) && (p0 > lx) && (p0 < lx + 2.0f) && (p0 != 0.0f);
    bool v1 = (ky >= 0) && (ky < NT) && (p1 > ly) && (p1 < ly + 2.0f) && (p1 != 0.0f);
    if (!(v0 && v1)) return -1;
    fx = (p0 - lx) * 0.5f;                                   // (lp - left)/scale, exact
    fy = (p1 - ly) * 0.5f;
    return kx * NT + ky;
}

__global__ __launch_bounds__(TPB)
void fused_kernel(const float* __restrict__ locs,
                  const float* __restrict__ fluxes,
                  float* __restrict__ out) {
    __shared__ __align__(16) float s_buf[SM_TOT];   // staged output chunk
    __shared__ int      s_g[TPB];                   // cell id per slot (if mask set)
    __shared__ unsigned s_mask[NWARP];              // per-warp acceptance ballots

    const int t  = threadIdx.x;
    const int g0 = blockIdx.x * CHUNK;
    const int g1 = min(g0 + CHUNK, BP);
    const int n  = g1 - g0;             // multiple of 4 (last block: 100)

    // ---- front-issue ALL input loads; L2 latency overlaps SMEM zeroing ----
    const int b_lo = g0 / PT;
    const int b_hi = (g1 - 1) / PT;                // <= b_lo + 1
    const int i_lo = b_lo * NSRC;
    const int span = (b_hi + 1) * NSRC - i_lo;     // <= 200 <= TPB
    const int idx  = i_lo + t;
    const bool has = (t < span);
    float2 l = make_float2(0.f, 0.f);
    float fv0 = 0.f, fv1 = 0.f, fv2 = 0.f, fv3 = 0.f, fv4 = 0.f;
    if (has) {
        l = __ldg(&((const float2*)locs)[idx]);
        const float* __restrict__ fl = fluxes + idx * NFLUX;
        fv0 = __ldg(fl + 0); fv1 = __ldg(fl + 1); fv2 = __ldg(fl + 2);
        fv3 = __ldg(fl + 3); fv4 = __ldg(fl + 4);
    }

    // ---- Phase A: zero the SMEM staging buffer (1173 float4, 5 rounds) ----
    {
        const float4 z = make_float4(0.f, 0.f, 0.f, 0.f);
        float4* __restrict__ b4 = (float4*)s_buf;
        #pragma unroll
        for (int i = t; i < SM_TOT / 4; i += TPB) b4[i] = z;
    }

    // ---- Phase B: classify (ballot scheme, validated in R9) ----
    float fx = 0.f, fy = 0.f;
    int   g  = -1;
    if (has) {
        int tile = map_source(l.x, l.y, fx, fy);
        if (tile >= 0) {
            int b = b_lo + (t >= NSRC ? 1 : 0);    // idx/NSRC without divide
            int gg = b * PT + tile;
            if (gg >= g0 && gg < g1) g = gg;
        }
    }
    const bool acc = (g >= 0);
    unsigned m = __ballot_sync(0xFFFFFFFFu, acc);
    if ((t & 31) == 0) s_mask[t >> 5] = m;
    if (acc) s_g[t] = g;

    __syncthreads();   // zeros + s_g/s_mask visible before scatter

    // ---- Phase C: rank via mask walk; scatter payload into SMEM ----
    if (acc) {
        int count = 0, rank = 0;
        #pragma unroll
        for (int w = 0; w < NWARP; w++) {
            unsigned mw = s_mask[w];
            while (mw) {
                int bi = __ffs(mw) - 1;
                mw &= mw - 1;
                int j = (w << 5) + bi;
                if (s_g[j] == g) { count++; rank += (j < t); }
            }
        }
        const int c = g - g0;
        if (rank == 0)
            s_buf[SM_N + c] = (float)(count < 2 ? count : 2);   // min(n, MAXDET)
        if (rank < 2) {
            s_buf[SM_L + 4 * c + 2 * rank + 0] = fx;
            s_buf[SM_L + 4 * c + 2 * rank + 1] = fy;
            int fb = SM_F + 10 * c + 5 * rank;
            s_buf[fb + 0] = fv0;
            s_buf[fb + 1] = fv1;
            s_buf[fb + 2] = fv2;
            s_buf[fb + 3] = fv3;
            s_buf[fb + 4] = fv4;
            s_buf[SM_I + 2 * c + rank] = 1.0f;
        }
    }

    // make generic-proxy SMEM writes visible to the async (bulk-copy) proxy
    asm volatile("fence.proxy.async.shared::cta;" ::: "memory");
    __syncthreads();

    // ---- Phase D: one thread issues 4 bulk copies; engine streams to L2 ----
    if (t == 0) {
        const uint32_t sb = smem_u32(s_buf);
        bulk_store_s2g(out + g0,               sb + SM_N * 4, (uint32_t)(4  * n));
        bulk_store_s2g(out + OFF_L + 4  * g0,  sb + SM_L * 4, (uint32_t)(16 * n));
        bulk_store_s2g(out + OFF_F + 10 * g0,  sb + SM_F * 4, (uint32_t)(40 * n));
        bulk_store_s2g(out + OFF_I + 2  * g0,  sb + SM_I * 4, (uint32_t)(8  * n));
        asm volatile("cp.async.bulk.commit_group;" ::: "memory");
        asm volatile("cp.async.bulk.wait_group 0;" ::: "memory");
    }
}

extern "C" void kernel_launch(void* const* d_in, const int* in_sizes, int n_in,
                              void* d_out, int out_size) {
    const float* locs   = (const float*)d_in[0];   // (16, 100, 2) f32
    const float* fluxes = (const float*)d_in[1];   // (16, 100, 5) f32
    fused_kernel<<<GRID, TPB>>>(locs, fluxes, (float*)d_out);
}

// round 11
// speedup vs baseline: 1.0156x; 1.0156x over previous
#include <cuda_runtime.h>
#include <cstdint>

// Problem constants (SLEN=208, PTILE=8, STEP=2, EDGE=3, MAXDET=2)
#define BATCH 16
#define NSRC  100
#define NFLUX 5
#define NT    101                 // tiles per dim
#define PT    (NT * NT)           // 10201
#define BP    (BATCH * PT)        // 163216
// Output sections (float32, concatenated):
//   n [BP] | locs [BP*4] | fluxes [BP*10] | is_on [BP*2]
#define OFF_L (BP)                 // 163216  (mult of 8)
#define OFF_F (OFF_L + BP * 4)     // 816080  (mult of 8)
#define OFF_I (OFF_F + BP * 10)    // 2448240 (mult of 8)

#define TPB    256
#define NWARP  (TPB / 32)
#define CHUNK  280                         // mult of 8, < PT (spans <= 2 batches)
#define GRID   ((BP + CHUNK - 1) / CHUNK)  // 583: ~4 blocks/SM, single wave

// 256-bit zero store (sm_100+: st.global.v8.f32)
__device__ __forceinline__ void stg256_zero(float* p) {
    asm volatile("st.global.v8.f32 [%0], {%1,%1,%1,%1,%1,%1,%1,%1};"
                 :: "l"(p), "f"(0.0f) : "memory");
}

// Map pixel coords -> (tile, fx, fy); returns tile or -1. Bit-identical to R1.
__device__ __forceinline__ int map_source(float l0, float l1, float& fx, float& fy) {
    float p0 = l0 * 207.0f;                                  // SLEN-1
    float p1 = l1 * 207.0f;
    int kx = (int)floorf((p0 - 2.5f) * 0.5f);
    int ky = (int)floorf((p1 - 2.5f) * 0.5f);
    float lx = 2.0f * (float)kx + 2.5f;                      // exact fp32
    float ly = 2.0f * (float)ky + 2.5f;
    bool v0 = (kx >= 0) && (kx < NT) && (p0 > lx) && (p0 < lx + 2.0f) && (p0 != 0.0f);
    bool v1 = (ky >= 0) && (ky < NT) && (p1 > ly) && (p1 < ly + 2.0f) && (p1 != 0.0f);
    if (!(v0 && v1)) return -1;
    fx = (p0 - lx) * 0.5f;                                   // (lp - left)/scale, exact
    fy = (p1 - ly) * 0.5f;
    return kx * NT + ky;
}

__global__ __launch_bounds__(TPB)
void fused_kernel(const float* __restrict__ locs,
                  const float* __restrict__ fluxes,
                  float* __restrict__ out) {
    __shared__ int      s_g[TPB];       // cell id per slot (valid iff ballot bit set)
    __shared__ unsigned s_mask[NWARP];  // per-warp acceptance ballots

    const int t  = threadIdx.x;
    const int g0 = blockIdx.x * CHUNK;
    const int g1 = min(g0 + CHUNK, BP);
    const int n  = g1 - g0;             // multiple of 8 (last block: 256)

    // ---- front-issue ALL input loads; L2 latency overlaps the fill ----
    const int b_lo = g0 / PT;
    const int b_hi = (g1 - 1) / PT;                // <= b_lo + 1
    const int i_lo = b_lo * NSRC;
    const int span = (b_hi + 1) * NSRC - i_lo;     // <= 200 <= TPB
    const int idx  = i_lo + t;
    const bool has = (t < span);
    float2 l = make_float2(0.f, 0.f);
    float fv0 = 0.f, fv1 = 0.f, fv2 = 0.f, fv3 = 0.f, fv4 = 0.f;
    if (has) {
        l = __ldg(&((const float2*)locs)[idx]);
        const float* __restrict__ fl = fluxes + idx * NFLUX;
        fv0 = __ldg(fl + 0); fv1 = __ldg(fl + 1); fv2 = __ldg(fl + 2);
        fv3 = __ldg(fl + 3); fv4 = __ldg(fl + 4);
    }

    // ---- Phase A: zero the 4 per-section slices; 5 predicated STG.256 ----
    // All bases 32B-aligned (g0 mult of 8, section offsets mult of 8),
    // all counts exact v8 multiples.
    {
        float* __restrict__ pN = out + g0;
        float* __restrict__ pL = out + OFF_L + 4  * g0;
        float* __restrict__ pF = out + OFF_F + 10 * g0;
        float* __restrict__ pI = out + OFF_I + 2  * g0;
        const int cN = n >> 3;          // <= 35   v8-stores
        const int cL = n >> 1;          // <= 140
        const int cF = (10 * n) >> 3;   // <= 350
        const int cI = n >> 2;          // <= 70
        if (t       < cN) stg256_zero(pN + 8 * t);
        if (t       < cL) stg256_zero(pL + 8 * t);
        if (t       < cF) stg256_zero(pF + 8 * t);
        if (t + TPB < cF) stg256_zero(pF + 8 * (t + TPB));
        if (t       < cI) stg256_zero(pI + 8 * t);
    }

    // ---- Phase B: classify (no atomics). Slot = thread id. ----
    float fx = 0.f, fy = 0.f;
    int   g  = -1;
    if (has) {
        int tile = map_source(l.x, l.y, fx, fy);
        if (tile >= 0) {
            int b = b_lo + (t >= NSRC ? 1 : 0);    // idx/NSRC without divide
            int gg = b * PT + tile;
            if (gg >= g0 && gg < g1) g = gg;
        }
    }
    const bool acc = (g >= 0);
    unsigned m = __ballot_sync(0xFFFFFFFFu, acc);
    if ((t & 31) == 0) s_mask[t >> 5] = m;         // every warp publishes
    if (acc) s_g[t] = g;                           // only accepted slots are read

    __syncthreads();   // ONE barrier: shared visibility + zero/payload WAW order

    // ---- Phase C: rank by walking the ~14 mask bits; payload from registers ----
    if (acc) {
        int count = 0, rank = 0;
        #pragma unroll
        for (int w = 0; w < NWARP; w++) {
            unsigned mw = s_mask[w];
            while (mw) {
                int bi = __ffs(mw) - 1;
                mw &= mw - 1;
                int j  = (w << 5) + bi;
                if (s_g[j] == g) { count++; rank += (j < t); }
            }
        }

        if (rank == 0)
            out[g] = (float)(count < 2 ? count : 2);     // min(n, MAXDET)

        if (rank < 2) {
            *(float2*)(out + OFF_L + 4 * g + 2 * rank) = make_float2(fx, fy);

            int fb = OFF_F + 10 * g + 5 * rank;
            out[fb + 0] = fv0;
            out[fb + 1] = fv1;
            out[fb + 2] = fv2;
            out[fb + 3] = fv3;
            out[fb + 4] = fv4;

            out[OFF_I + 2 * g + rank] = 1.0f;
        }
    }
}

extern "C" void kernel_launch(void* const* d_in, const int* in_sizes, int n_in,
                              void* d_out, int out_size) {
    const float* locs   = (const float*)d_in[0];   // (16, 100, 2) f32
    const float* fluxes = (const float*)d_in[1];   // (16, 100, 5) f32
    fused_kernel<<<GRID, TPB>>>(locs, fluxes, (float*)d_out);
}

// round 13
// speedup vs baseline: 1.2500x; 1.2308x over previous
#include <cuda_runtime.h>

// Problem constants (SLEN=208, PTILE=8, STEP=2, EDGE=3, MAXDET=2)
#define BATCH 16
#define NSRC  100
#define NFLUX 5
#define NT    101                  // tiles per dim
#define PT    (NT * NT)            // 10201
#define BP    (BATCH * PT)         // 163216
// Output sections (float32, concatenated):
//   n [BP] | locs [BP*4] | fluxes [BP*10] | is_on [BP*2]
#define OFF_L (BP)                 // 163216  (mult of 4)
#define OFF_F (OFF_L + BP * 4)     // 816080  (mult of 4)
#define OFF_I (OFF_F + BP * 10)    // 2448240 (mult of 4)

#define TPB    256
#define NWARP  (TPB / 32)
#define CHUNK  276                         // mult of 4, < PT (spans <= 2 batches)
#define GRID   ((BP + CHUNK - 1) / CHUNK)  // 592: 4 blocks/SM, single wave

// Map pixel coords -> (tile, fx, fy); returns tile or -1. Bit-identical to R1.
__device__ __forceinline__ int map_source(float l0, float l1, float& fx, float& fy) {
    float p0 = l0 * 207.0f;                                  // SLEN-1
    float p1 = l1 * 207.0f;
    int kx = (int)floorf((p0 - 2.5f) * 0.5f);
    int ky = (int)floorf((p1 - 2.5f) * 0.5f);
    float lx = 2.0f * (float)kx + 2.5f;                      // exact fp32
    float ly = 2.0f * (float)ky + 2.5f;
    bool v0 = (kx >= 0) && (kx < NT) && (p0 > lx) && (p0 < lx + 2.0f) && (p0 != 0.0f);
    bool v1 = (ky >= 0) && (ky < NT) && (p1 > ly) && (p1 < ly + 2.0f) && (p1 != 0.0f);
    if (!(v0 && v1)) return -1;
    fx = (p0 - lx) * 0.5f;                                   // (lp - left)/scale, exact
    fy = (p1 - ly) * 0.5f;
    return kx * NT + ky;
}

__global__ __launch_bounds__(TPB)
void fused_kernel(const float* __restrict__ locs,
                  const float* __restrict__ fluxes,
                  float* __restrict__ out) {
    __shared__ int      s_g[TPB];       // cell id per slot (valid iff ballot bit set)
    __shared__ unsigned s_mask[NWARP];  // per-warp acceptance ballots

    const int t  = threadIdx.x;
    const int g0 = blockIdx.x * CHUNK;
    const int g1 = min(g0 + CHUNK, BP);
    const int n  = g1 - g0;             // multiple of 4 (last block: 100)

    // ---- front-issue ALL input loads unconditionally (clamped index):
    //      loads in flight at high MLP from cycle 0, overlapping the fill.
    //      All scalar/8B loads: only 4B/8B alignment required. ----
    const int b_lo = g0 / PT;
    const int b_hi = (g1 - 1) / PT;                // <= b_lo + 1
    const int i_lo = b_lo * NSRC;
    const int span = (b_hi + 1) * NSRC - i_lo;     // <= 200 <= TPB
    const bool has = (t < span);
    const int idx  = i_lo + (has ? t : 0);         // clamp: safe, unused if !has
    const float2 l = __ldg(&((const float2*)locs)[idx]);   // 8B-aligned (idx*8)
    const float* __restrict__ fl = fluxes + idx * NFLUX;
    const float fv0 = __ldg(fl + 0);
    const float fv1 = __ldg(fl + 1);
    const float fv2 = __ldg(fl + 2);
    const float fv3 = __ldg(fl + 3);
    const float fv4 = __ldg(fl + 4);

    // ---- Phase A: zero the 4 per-section slices; <=7 predicated STG.128 ----
    {
        const float4 z = make_float4(0.f, 0.f, 0.f, 0.f);
        float4* __restrict__ pN = (float4*)(out + g0);
        float4* __restrict__ pL = (float4*)(out + OFF_L + 4  * g0);
        float4* __restrict__ pF = (float4*)(out + OFF_F + 10 * g0);
        float4* __restrict__ pI = (float4*)(out + OFF_I + 2  * g0);
        const int cN = n >> 2;          // <= 69
        const int cL = n;               // <= 276
        const int cF = (10 * n) >> 2;   // <= 690
        const int cI = n >> 1;          // <= 138
        if (t           < cN) pN[t]           = z;
        if (t           < cL) pL[t]           = z;
        if (t + TPB     < cL) pL[t + TPB]     = z;
        if (t           < cF) pF[t]           = z;
        if (t + TPB     < cF) pF[t + TPB]     = z;
        if (t + 2 * TPB < cF) pF[t + 2 * TPB] = z;
        if (t           < cI) pI[t]           = z;
    }

    // ---- Phase B: classify (no atomics). Slot = thread id. ----
    float fx = 0.f, fy = 0.f;
    int   g  = -1;
    if (has) {
        int tile = map_source(l.x, l.y, fx, fy);
        if (tile >= 0) {
            int b = b_lo + (t >= NSRC ? 1 : 0);    // idx/NSRC without divide
            int gg = b * PT + tile;
            if (gg >= g0 && gg < g1) g = gg;
        }
    }
    const bool acc = (g >= 0);
    unsigned m = __ballot_sync(0xFFFFFFFFu, acc);
    if ((t & 31) == 0) s_mask[t >> 5] = m;         // every warp publishes
    if (acc) s_g[t] = g;                           // only accepted slots are read

    __syncthreads();   // ONE barrier: shared visibility + zero/payload WAW order

    // ---- Phase C: rank by walking the ~14 mask bits; payload from registers ----
    if (acc) {
        int count = 0, rank = 0;
        #pragma unroll
        for (int w = 0; w < NWARP; w++) {
            unsigned mw = s_mask[w];
            while (mw) {
                int bi = __ffs(mw) - 1;
                mw &= mw - 1;
                int j  = (w << 5) + bi;
                if (s_g[j] == g) { count++; rank += (j < t); }
            }
        }

        if (rank == 0)
            out[g] = (float)(count < 2 ? count : 2);     // min(n, MAXDET)

        if (rank < 2) {
            *(float2*)(out + OFF_L + 4 * g + 2 * rank) = make_float2(fx, fy);

            int fb = OFF_F + 10 * g + 5 * rank;    // base only 4B-aligned: scalars
            out[fb + 0] = fv0;
            out[fb + 1] = fv1;
            out[fb + 2] = fv2;
            out[fb + 3] = fv3;
            out[fb + 4] = fv4;

            out[OFF_I + 2 * g + rank] = 1.0f;
        }
    }
}

extern "C" void kernel_launch(void* const* d_in, const int* in_sizes, int n_in,
                              void* d_out, int out_size) {
    const float* locs   = (const float*)d_in[0];   // (16, 100, 2) f32
    const float* fluxes = (const float*)d_in[1];   // (16, 100, 5) f32
    fused_kernel<<<GRID, TPB>>>(locs, fluxes, (float*)d_out);
}